// round 6
// baseline (speedup 1.0000x reference)
#include <cuda_runtime.h>

#define THREADS 256
#define L 2500
#define HALF 1251          // bins 0..1250
#define PATCHES 50
#define TWN 500            // master twiddle table: W_2500^j, j=0..499

typedef unsigned long long u64;

__device__ __forceinline__ float2 cmul(float2 a, float2 b) {
    return make_float2(a.x * b.x - a.y * b.y, a.x * b.y + a.y * b.x);
}

// radix-5 constants (w = e^{-2pi i/5})
#define CR1 ( 0.30901699437494742f)
#define CR2 (-0.80901699437494742f)
#define SI1 ( 0.95105651629515357f)
#define SI2 ( 0.58778525229247314f)

// Stockham DIF radix-5 stage, natural-order autosort. WORK = 500 each.
template <int NN, int SS>
__device__ __forceinline__ void stage5(const float2* __restrict__ X, float2* __restrict__ Y,
                                       const float2* __restrict__ tw, int tid) {
    constexpr int M = NN / 5;
    constexpr int STRIDE = 2500 / NN;
    for (int w = tid; w < M * SS; w += THREADS) {
        const int q = w % SS;
        const int p = w / SS;
        float2 a0 = X[q + SS * p];
        float2 a1 = X[q + SS * (p + M)];
        float2 a2 = X[q + SS * (p + 2 * M)];
        float2 a3 = X[q + SS * (p + 3 * M)];
        float2 a4 = X[q + SS * (p + 4 * M)];
        float2 t1 = make_float2(a1.x + a4.x, a1.y + a4.y);
        float2 t2 = make_float2(a2.x + a3.x, a2.y + a3.y);
        float2 t3 = make_float2(a1.x - a4.x, a1.y - a4.y);
        float2 t4 = make_float2(a2.x - a3.x, a2.y - a3.y);
        float2 c0 = make_float2(a0.x + t1.x + t2.x, a0.y + t1.y + t2.y);
        float2 m1 = make_float2(a0.x + CR1 * t1.x + CR2 * t2.x, a0.y + CR1 * t1.y + CR2 * t2.y);
        float2 m2 = make_float2(a0.x + CR2 * t1.x + CR1 * t2.x, a0.y + CR2 * t1.y + CR1 * t2.y);
        float2 s1 = make_float2(SI1 * t3.x + SI2 * t4.x, SI1 * t3.y + SI2 * t4.y);
        float2 s2 = make_float2(SI2 * t3.x - SI1 * t4.x, SI2 * t3.y - SI1 * t4.y);
        float2 c1 = make_float2(m1.x + s1.y, m1.y - s1.x);
        float2 c4 = make_float2(m1.x - s1.y, m1.y + s1.x);
        float2 c2 = make_float2(m2.x + s2.y, m2.y - s2.x);
        float2 c3 = make_float2(m2.x - s2.y, m2.y + s2.x);
        float2 w1 = tw[p * STRIDE];
        float2 w2 = cmul(w1, w1);
        float2 w3 = cmul(w2, w1);
        float2 w4 = cmul(w2, w2);
        const int ob = q + SS * 5 * p;
        Y[ob]          = c0;
        Y[ob + SS]     = cmul(c1, w1);
        Y[ob + 2 * SS] = cmul(c2, w2);
        Y[ob + 3 * SS] = cmul(c3, w3);
        Y[ob + 4 * SS] = cmul(c4, w4);
    }
}

// Branchless insert of key x into sorted triple (k0 >= k1 >= k2).
__device__ __forceinline__ void ins(u64 x, u64& k0, u64& k1, u64& k2) {
    u64 m0 = (k0 < x) ? k0 : x;  k0 = (k0 < x) ? x : k0;
    u64 m1 = (k1 < m0) ? k1 : m0; k1 = (k1 < m0) ? m0 : k1;
    k2 = (k2 < m1) ? m1 : k2;
}

__global__ __launch_bounds__(THREADS)
void TimeSeriesWeighting_kernel(const float* __restrict__ x,
                                const float* __restrict__ wscal,
                                float* __restrict__ out) {
    __shared__ float2 bufA[L];
    __shared__ float2 bufB[L];
    __shared__ float2 tw[TWN];
    __shared__ u64 wkeys[2][THREADS / 32][3];   // per-warp triples, [batch][warp][rank]
    __shared__ int top_idx[2][3];

    const int tid = threadIdx.x;
    const long long b0 = 2LL * blockIdx.x;

    // Pack two batches' head-0 rows: z = x_a + i*x_b (rows 30000 floats apart, 16B-aligned)
    const float4* sa = reinterpret_cast<const float4*>(x + b0 * 30000);
    const float4* sb = reinterpret_cast<const float4*>(x + (b0 + 1) * 30000);
    for (int i = tid; i < 625; i += THREADS) {
        float4 va = sa[i], vb = sb[i];
        int j = i * 4;
        bufA[j]     = make_float2(va.x, vb.x);
        bufA[j + 1] = make_float2(va.y, vb.y);
        bufA[j + 2] = make_float2(va.z, vb.z);
        bufA[j + 3] = make_float2(va.w, vb.w);
    }
    // Master twiddle table via fast MUFU sincos (ranking-safe)
    for (int j = tid; j < TWN; j += THREADS) {
        float sn, cs;
        __sincosf(-6.283185307179586f * (float)j * (1.0f / 2500.0f), &sn, &cs);
        tw[j] = make_float2(cs, sn);
    }
    __syncthreads();

    // 2500 = 5*5*5*5*4 mixed-radix Stockham (autosort -> natural order)
    stage5<2500, 1>(bufA, bufB, tw, tid);  __syncthreads();
    stage5<500, 5>(bufB, bufA, tw, tid);   __syncthreads();
    stage5<100, 25>(bufA, bufB, tw, tid);  __syncthreads();
    stage5<20, 125>(bufB, bufA, tw, tid);  __syncthreads();
    // final radix-4 stage: NN=4, SS=625, twiddle = 1
    for (int q = tid; q < 625; q += THREADS) {
        float2 a0 = bufA[q], a1 = bufA[q + 625], a2 = bufA[q + 1250], a3 = bufA[q + 1875];
        float2 e0 = make_float2(a0.x + a2.x, a0.y + a2.y);
        float2 e1 = make_float2(a0.x - a2.x, a0.y - a2.y);
        float2 o0 = make_float2(a1.x + a3.x, a1.y + a3.y);
        float2 o1 = make_float2(a1.x - a3.x, a1.y - a3.y);
        bufB[q]        = make_float2(e0.x + o0.x, e0.y + o0.y);
        bufB[q + 625]  = make_float2(e1.x + o1.y, e1.y - o1.x);
        bufB[q + 1250] = make_float2(e0.x - o0.x, e0.y - o0.y);
        bufB[q + 1875] = make_float2(e1.x - o1.y, e1.y + o1.x);
    }
    __syncthreads();

    // Fused packed-split + power + top-3 (single pass, branchless u64 keys).
    //   pw_a[k] ∝ |Z[k] + conj(Z[2500-k])|^2 ,  pw_b[k] ∝ |Z[k] - conj(Z[2500-k])|^2
    // key = (float_bits << 32) | ~k  ->  max = (value desc, index asc) = lax.top_k order
    u64 a0k = 0, a1k = 0, a2k = 0;   // batch a triple (sorted desc)
    u64 c0k = 0, c1k = 0, c2k = 0;   // batch b triple
    for (int k = tid; k < HALF; k += THREADS) {
        float2 zk = bufB[k];
        float2 zm = bufB[k == 0 ? 0 : (L - k)];
        float sx = zk.x + zm.x, sy = zk.y - zm.y;
        float dx = zk.x - zm.x, dy = zk.y + zm.y;
        float va = sx * sx + sy * sy;
        float vb = dx * dx + dy * dy;
        u64 low = (u64)(~(unsigned int)k);
        ins(((u64)__float_as_uint(va) << 32) | low, a0k, a1k, a2k);
        ins(((u64)__float_as_uint(vb) << 32) | low, c0k, c1k, c2k);
    }
    // warp-level merge of sorted triples
    #pragma unroll
    for (int off = 16; off > 0; off >>= 1) {
        u64 t0 = __shfl_down_sync(0xffffffffu, a0k, off);
        u64 t1 = __shfl_down_sync(0xffffffffu, a1k, off);
        u64 t2 = __shfl_down_sync(0xffffffffu, a2k, off);
        ins(t0, a0k, a1k, a2k); ins(t1, a0k, a1k, a2k); ins(t2, a0k, a1k, a2k);
        u64 u0 = __shfl_down_sync(0xffffffffu, c0k, off);
        u64 u1 = __shfl_down_sync(0xffffffffu, c1k, off);
        u64 u2 = __shfl_down_sync(0xffffffffu, c2k, off);
        ins(u0, c0k, c1k, c2k); ins(u1, c0k, c1k, c2k); ins(u2, c0k, c1k, c2k);
    }
    const int wid = tid >> 5;
    if ((tid & 31) == 0) {
        wkeys[0][wid][0] = a0k; wkeys[0][wid][1] = a1k; wkeys[0][wid][2] = a2k;
        wkeys[1][wid][0] = c0k; wkeys[1][wid][1] = c1k; wkeys[1][wid][2] = c2k;
    }
    __syncthreads();
    // two parallel final merges: thread 0 -> batch a, thread 32 -> batch b
    if (tid == 0 || tid == 32) {
        const int g = (tid == 32);
        u64 f0 = wkeys[g][0][0], f1 = wkeys[g][0][1], f2 = wkeys[g][0][2];
        #pragma unroll
        for (int wq = 1; wq < THREADS / 32; wq++) {
            ins(wkeys[g][wq][0], f0, f1, f2);
            ins(wkeys[g][wq][1], f0, f1, f2);
            ins(wkeys[g][wq][2], f0, f1, f2);
        }
        top_idx[g][0] = ~(unsigned int)f0;
        top_idx[g][1] = ~(unsigned int)f1;
        top_idx[g][2] = ~(unsigned int)f2;
    }
    __syncthreads();

    // Full-spectrum ranks {0, 2} from half-spectrum top-3 with pair multiplicity:
    // DC (0) and Nyquist (1250) appear once; other bins twice (k, 2500-k).
    const int g = tid >> 7;        // threads [0,128) -> batch a, [128,256) -> batch b
    const int lt = tid & 127;
    const int h0 = top_idx[g][0], h1 = top_idx[g][1], h2 = top_idx[g][2];
    const bool h0_pair = (h0 != 0 && h0 != 1250);
    const bool h1_pair = (h1 != 0 && h1 != 1250);
    const int ka = h0;
    const int kb = (h0_pair || h1_pair) ? h1 : h2;

    if (lt < PATCHES) {
        const float wgt = 12.0f * wscal[0];  // N * weights
        const int start = lt * 50;
        int cnt = 0;
        if (ka != 0) {
            int p = L / ka;
            int fm = ((start + p - 1) / p) * p;
            cnt += (fm < start + 50);
        }
        if (kb != 0) {
            int p = L / kb;
            int fm = ((start + p - 1) / p) * p;
            cnt += (fm < start + 50);
        }
        out[(b0 + g) * PATCHES + lt] = wgt * (float)cnt;
    }
}

extern "C" void kernel_launch(void* const* d_in, const int* in_sizes, int n_in,
                              void* d_out, int out_size) {
    const float* x = (const float*)d_in[0];
    const float* w = (const float*)d_in[1];
    int xs = in_sizes[0];
    if (n_in >= 2 && in_sizes[0] < in_sizes[1]) {  // order-robust: scalar vs big tensor
        x = (const float*)d_in[1];
        w = (const float*)d_in[0];
        xs = in_sizes[1];
    }
    const int B = xs / (12 * L);   // 1024
    TimeSeriesWeighting_kernel<<<B / 2, THREADS>>>(x, w, (float*)d_out);
}

// round 7
// speedup vs baseline: 1.2374x; 1.2374x over previous
#include <cuda_runtime.h>

#define THREADS 256
#define L 2500
#define HALF 1251          // bins 0..1250
#define PATCHES 50
#define TWN 500            // master twiddle table: W_2500^j, j=0..499
#define GROUP 128          // threads per batch in the search phase

__device__ float2 g_tw[TWN];   // shared by all CTAs, filled by init kernel

__device__ __forceinline__ float2 cmul(float2 a, float2 b) {
    return make_float2(a.x * b.x - a.y * b.y, a.x * b.y + a.y * b.x);
}

// radix-5 constants (w = e^{-2pi i/5})
#define CR1 ( 0.30901699437494742f)
#define CR2 (-0.80901699437494742f)
#define SI1 ( 0.95105651629515357f)
#define SI2 ( 0.58778525229247314f)

__global__ void tw_init_kernel() {
    int j = blockIdx.x * blockDim.x + threadIdx.x;
    if (j < TWN) {
        float sn, cs;
        sincosf(-6.283185307179586f * (float)j / 2500.0f, &sn, &cs);
        g_tw[j] = make_float2(cs, sn);
    }
}

// Stockham DIF radix-5 stage, natural-order autosort. WORK = 500 each.
// Twiddles read from the global table (L1-resident, broadcast-heavy).
template <int NN, int SS>
__device__ __forceinline__ void stage5(const float2* __restrict__ X, float2* __restrict__ Y, int tid) {
    constexpr int M = NN / 5;
    constexpr int STRIDE = 2500 / NN;
    for (int w = tid; w < M * SS; w += THREADS) {
        const int q = w % SS;
        const int p = w / SS;
        float2 a0 = X[q + SS * p];
        float2 a1 = X[q + SS * (p + M)];
        float2 a2 = X[q + SS * (p + 2 * M)];
        float2 a3 = X[q + SS * (p + 3 * M)];
        float2 a4 = X[q + SS * (p + 4 * M)];
        float2 t1 = make_float2(a1.x + a4.x, a1.y + a4.y);
        float2 t2 = make_float2(a2.x + a3.x, a2.y + a3.y);
        float2 t3 = make_float2(a1.x - a4.x, a1.y - a4.y);
        float2 t4 = make_float2(a2.x - a3.x, a2.y - a3.y);
        float2 c0 = make_float2(a0.x + t1.x + t2.x, a0.y + t1.y + t2.y);
        float2 m1 = make_float2(a0.x + CR1 * t1.x + CR2 * t2.x, a0.y + CR1 * t1.y + CR2 * t2.y);
        float2 m2 = make_float2(a0.x + CR2 * t1.x + CR1 * t2.x, a0.y + CR2 * t1.y + CR1 * t2.y);
        float2 s1 = make_float2(SI1 * t3.x + SI2 * t4.x, SI1 * t3.y + SI2 * t4.y);
        float2 s2 = make_float2(SI2 * t3.x - SI1 * t4.x, SI2 * t3.y - SI1 * t4.y);
        float2 c1 = make_float2(m1.x + s1.y, m1.y - s1.x);
        float2 c4 = make_float2(m1.x - s1.y, m1.y + s1.x);
        float2 c2 = make_float2(m2.x + s2.y, m2.y - s2.x);
        float2 c3 = make_float2(m2.x - s2.y, m2.y + s2.x);
        float2 w1 = g_tw[p * STRIDE];
        float2 w2 = cmul(w1, w1);
        float2 w3 = cmul(w2, w1);
        float2 w4 = cmul(w2, w2);
        const int ob = q + SS * 5 * p;
        Y[ob]          = c0;
        Y[ob + SS]     = cmul(c1, w1);
        Y[ob + 2 * SS] = cmul(c2, w2);
        Y[ob + 3 * SS] = cmul(c3, w3);
        Y[ob + 4 * SS] = cmul(c4, w4);
    }
}

__global__ __launch_bounds__(THREADS)
void TimeSeriesWeighting_kernel(const float* __restrict__ x,
                                const float* __restrict__ wscal,
                                float* __restrict__ out) {
    __shared__ float2 bufA[L];
    __shared__ float2 bufB[L];
    __shared__ float s_v[THREADS / 32];
    __shared__ int   s_i[THREADS / 32];
    __shared__ int   top_idx[2][3];

    const int tid = threadIdx.x;
    const long long b0 = 2LL * blockIdx.x;

    // Pack two batches' head-0 rows: z = x_a + i*x_b (rows 30000 floats apart, 16B-aligned)
    const float4* sa = reinterpret_cast<const float4*>(x + b0 * 30000);
    const float4* sb = reinterpret_cast<const float4*>(x + (b0 + 1) * 30000);
    for (int i = tid; i < 625; i += THREADS) {
        float4 va = sa[i], vb = sb[i];
        int j = i * 4;
        bufA[j]     = make_float2(va.x, vb.x);
        bufA[j + 1] = make_float2(va.y, vb.y);
        bufA[j + 2] = make_float2(va.z, vb.z);
        bufA[j + 3] = make_float2(va.w, vb.w);
    }
    __syncthreads();

    // 2500 = 5*5*5*5*4 mixed-radix Stockham (autosort -> natural order)
    stage5<2500, 1>(bufA, bufB, tid);  __syncthreads();
    stage5<500, 5>(bufB, bufA, tid);   __syncthreads();
    stage5<100, 25>(bufA, bufB, tid);  __syncthreads();
    stage5<20, 125>(bufB, bufA, tid);  __syncthreads();
    // final radix-4 stage: NN=4, SS=625, twiddle = 1
    for (int q = tid; q < 625; q += THREADS) {
        float2 a0 = bufA[q], a1 = bufA[q + 625], a2 = bufA[q + 1250], a3 = bufA[q + 1875];
        float2 e0 = make_float2(a0.x + a2.x, a0.y + a2.y);
        float2 e1 = make_float2(a0.x - a2.x, a0.y - a2.y);
        float2 o0 = make_float2(a1.x + a3.x, a1.y + a3.y);
        float2 o1 = make_float2(a1.x - a3.x, a1.y - a3.y);
        bufB[q]        = make_float2(e0.x + o0.x, e0.y + o0.y);
        bufB[q + 625]  = make_float2(e1.x + o1.y, e1.y - o1.x);
        bufB[q + 1250] = make_float2(e0.x - o0.x, e0.y - o0.y);
        bufB[q + 1875] = make_float2(e1.x - o1.y, e1.y + o1.x);
    }
    __syncthreads();

    // Split packed spectrum into two power spectra (uniform x4 factor, argmax-invariant):
    //   pw_a[k] = |Z[k] + conj(Z[N-k])|^2 ,  pw_b[k] = |Z[k] - conj(Z[N-k])|^2
    float* pa = reinterpret_cast<float*>(bufA);   // 1251 floats
    float* pb = pa + 1280;                        // 1251 floats (fits in bufA's 5000 floats)
    for (int k = tid; k < HALF; k += THREADS) {
        float2 zk = bufB[k];
        float2 zm = bufB[k == 0 ? 0 : (L - k)];
        float sx = zk.x + zm.x, sy = zk.y - zm.y;
        float dx = zk.x - zm.x, dy = zk.y + zm.y;
        pa[k] = sx * sx + sy * sy;
        pb[k] = dx * dx + dy * dy;
    }
    __syncthreads();

    // Top-3 half-spectrum bins per batch; group 0 = threads 0..127 (batch a),
    // group 1 = threads 128..255 (batch b). 3 exclusion passes.
    const int g = tid >> 7;
    const int lt = tid & 127;
    const float* pw = g ? pb : pa;
    for (int r = 0; r < 3; r++) {
        const int e0 = (r > 0) ? top_idx[g][0] : -1;
        const int e1 = (r > 1) ? top_idx[g][1] : -1;
        float bv = -1.0f;
        int bi = 0x7fffffff;
        for (int k = lt; k < HALF; k += GROUP) {
            if (k == e0 || k == e1) continue;
            float v = pw[k];
            if (v > bv || (v == bv && k < bi)) { bv = v; bi = k; }
        }
        #pragma unroll
        for (int off = 16; off > 0; off >>= 1) {
            float ov = __shfl_down_sync(0xffffffffu, bv, off);
            int   oi = __shfl_down_sync(0xffffffffu, bi, off);
            if (ov > bv || (ov == bv && oi < bi)) { bv = ov; bi = oi; }
        }
        if ((tid & 31) == 0) { s_v[tid >> 5] = bv; s_i[tid >> 5] = bi; }
        __syncthreads();
        if (lt == 0) {
            const int base = g * 4;
            float fv = s_v[base]; int fi = s_i[base];
            #pragma unroll
            for (int wv = 1; wv < 4; wv++) {
                float v2 = s_v[base + wv]; int i2 = s_i[base + wv];
                if (v2 > fv || (v2 == fv && i2 < fi)) { fv = v2; fi = i2; }
            }
            top_idx[g][r] = fi;
        }
        __syncthreads();
    }

    // Full-spectrum ranks {0, 2} from half-spectrum top-3 with pair multiplicity:
    // DC (0) and Nyquist (1250) appear once; other bins twice (k, 2500-k).
    const int h0 = top_idx[g][0], h1 = top_idx[g][1], h2 = top_idx[g][2];
    const bool h0_pair = (h0 != 0 && h0 != 1250);
    const bool h1_pair = (h1 != 0 && h1 != 1250);
    const int ka = h0;
    const int kb = (h0_pair || h1_pair) ? h1 : h2;

    if (lt < PATCHES) {
        const float wgt = 12.0f * wscal[0];  // N * weights
        const int start = lt * 50;
        int cnt = 0;
        if (ka != 0) {
            int p = L / ka;
            int fm = ((start + p - 1) / p) * p;
            cnt += (fm < start + 50);
        }
        if (kb != 0) {
            int p = L / kb;
            int fm = ((start + p - 1) / p) * p;
            cnt += (fm < start + 50);
        }
        out[(b0 + g) * PATCHES + lt] = wgt * (float)cnt;
    }
}

extern "C" void kernel_launch(void* const* d_in, const int* in_sizes, int n_in,
                              void* d_out, int out_size) {
    const float* x = (const float*)d_in[0];
    const float* w = (const float*)d_in[1];
    int xs = in_sizes[0];
    if (n_in >= 2 && in_sizes[0] < in_sizes[1]) {  // order-robust: scalar vs big tensor
        x = (const float*)d_in[1];
        w = (const float*)d_in[0];
        xs = in_sizes[1];
    }
    const int B = xs / (12 * L);   // 1024
    tw_init_kernel<<<2, 256>>>();
    TimeSeriesWeighting_kernel<<<B / 2, THREADS>>>(x, w, (float*)d_out);
}